// round 1
// baseline (speedup 1.0000x reference)
#include <cuda_runtime.h>
#include <cuda_bf16.h>

#define NN 50000
#define NE 800000

// ---- device scratch (static: no allocation allowed) ----
__device__ float g_hf[(size_t)NN * 128];     // nfeat @ W_fc
__device__ float g_ssum[(size_t)NN * 128];   // segment_sum(efeat, dst)
__device__ float g_el[NN * 8];
__device__ float g_er[NN * 8];
__device__ float g_ex[(size_t)NE * 8];       // exp(leaky(el[src]+er[dst]))
__device__ float g_denom[NN * 8];
__device__ float g_indeg[NN];

__device__ __forceinline__ void red4(float* p, float4 v) {
    asm volatile("red.global.add.v4.f32 [%0], {%1,%2,%3,%4};"
                 :: "l"(p), "f"(v.x), "f"(v.y), "f"(v.z), "f"(v.w) : "memory");
}

// ---- init: zero accumulators, seed out with bias ----
__global__ void k_init(const float* __restrict__ bias, float* __restrict__ out) {
    int i = blockIdx.x * blockDim.x + threadIdx.x;
    int stride = gridDim.x * blockDim.x;
    for (int idx = i; idx < NN * 128; idx += stride) {
        g_ssum[idx] = 0.f;
        out[idx] = bias[idx & 127];
    }
    for (int idx = i; idx < NN * 8; idx += stride) g_denom[idx] = 0.f;
    for (int idx = i; idx < NN; idx += stride) g_indeg[idx] = 0.f;
}

// ---- pass 1: scatter-add efeat rows by dst; count in-degree ----
__global__ void k_ssum(const float* __restrict__ efeat, const int* __restrict__ dst) {
    long long t = (long long)blockIdx.x * blockDim.x + threadIdx.x;
    int e = (int)(t >> 5);
    if (e >= NE) return;
    int lane = threadIdx.x & 31;
    int d = __ldg(dst + e);
    float4 v = __ldg((const float4*)efeat + (size_t)e * 32 + lane);
    red4(g_ssum + (size_t)d * 128 + lane * 4, v);
    if (lane == 0) atomicAdd(g_indeg + d, 1.0f);
}

// ---- GEMM [rows,128] @ [128,128], fused epilogues ----
// MODE 0: A = nfeat, W = W_fc  -> g_hf, g_el, g_er
// MODE 1: A = g_ssum, W = W_e  -> out += he/max(deg,1) + b_e*(deg>0) + hf/(deg+1)
template <int MODE>
__global__ void __launch_bounds__(128)
k_gemm(const float* __restrict__ A, const float* __restrict__ W,
       const float* __restrict__ attn_l, const float* __restrict__ attn_r,
       const float* __restrict__ b_e, float* __restrict__ out) {
    __shared__ float4 rows4[32 * 32];   // 32 rows x 128 floats
    int col = threadIdx.x;              // 0..127 output column
    int row0 = blockIdx.x * 32;
    int nrows = NN - row0; if (nrows > 32) nrows = 32;

    const float* Ap = (MODE == 1) ? (const float*)g_ssum : A;
    const float4* A4 = (const float4*)Ap + (size_t)row0 * 32;
    for (int i = col; i < 32 * 32; i += 128)
        rows4[i] = (i < nrows * 32) ? __ldg(A4 + i) : make_float4(0.f, 0.f, 0.f, 0.f);
    __syncthreads();

    float acc[32];
#pragma unroll
    for (int r = 0; r < 32; r++) acc[r] = 0.f;

#pragma unroll 1
    for (int kt = 0; kt < 8; kt++) {
        float w[16];
#pragma unroll
        for (int i = 0; i < 16; i++) w[i] = __ldg(W + (kt * 16 + i) * 128 + col);
#pragma unroll
        for (int r = 0; r < 32; r++) {
            float4 v0 = rows4[r * 32 + kt * 4 + 0];
            float4 v1 = rows4[r * 32 + kt * 4 + 1];
            float4 v2 = rows4[r * 32 + kt * 4 + 2];
            float4 v3 = rows4[r * 32 + kt * 4 + 3];
            acc[r] += v0.x * w[0] + v0.y * w[1] + v0.z * w[2] + v0.w * w[3]
                    + v1.x * w[4] + v1.y * w[5] + v1.z * w[6] + v1.w * w[7]
                    + v2.x * w[8] + v2.y * w[9] + v2.z * w[10] + v2.w * w[11]
                    + v3.x * w[12] + v3.y * w[13] + v3.z * w[14] + v3.w * w[15];
        }
    }

    if (MODE == 0) {
        float al = __ldg(attn_l + col);
        float ar = __ldg(attn_r + col);
        for (int r = 0; r < nrows; r++) {
            int n = row0 + r;
            g_hf[(size_t)n * 128 + col] = acc[r];
            float l = acc[r] * al;
            float rr = acc[r] * ar;
#pragma unroll
            for (int o = 8; o; o >>= 1) {
                l += __shfl_down_sync(0xffffffffu, l, o, 16);
                rr += __shfl_down_sync(0xffffffffu, rr, o, 16);
            }
            if ((col & 15) == 0) {
                g_el[n * 8 + (col >> 4)] = l;
                g_er[n * 8 + (col >> 4)] = rr;
            }
        }
    } else {
        float be = __ldg(b_e + col);
        for (int r = 0; r < nrows; r++) {
            int n = row0 + r;
            float deg = g_indeg[n];
            float val = out[(size_t)n * 128 + col];
            val += acc[r] / fmaxf(deg, 1.f);          // (segsum(efeat)@W_e)/max(deg,1)
            val += (deg > 0.f) ? be : 0.f;            // b_e * deg/max(deg,1)
            val += g_hf[(size_t)n * 128 + col] / (deg + 1.f);  // skip term
            out[(size_t)n * 128 + col] = val;
        }
    }
}

// ---- pass 2: edge scores -> exp (softmax shift-invariant, skip segment max) ----
__global__ void k_score(const int* __restrict__ src, const int* __restrict__ dst) {
    int t = blockIdx.x * blockDim.x + threadIdx.x;
    int e = t >> 1;
    if (e >= NE) return;
    int half = t & 1;
    int s = __ldg(src + e);
    int d = __ldg(dst + e);
    float4 l4 = __ldg((const float4*)g_el + s * 2 + half);
    float4 r4 = __ldg((const float4*)g_er + d * 2 + half);
    float4 ex;
    float v;
    v = l4.x + r4.x; v = v > 0.f ? v : 0.2f * v; ex.x = __expf(v);
    v = l4.y + r4.y; v = v > 0.f ? v : 0.2f * v; ex.y = __expf(v);
    v = l4.z + r4.z; v = v > 0.f ? v : 0.2f * v; ex.z = __expf(v);
    v = l4.w + r4.w; v = v > 0.f ? v : 0.2f * v; ex.w = __expf(v);
    ((float4*)g_ex)[(size_t)e * 2 + half] = ex;
    red4(g_denom + d * 8 + half * 4, ex);
}

// ---- pass 3: aggregate a * h[src] into out[dst] (warp per edge) ----
__global__ void k_agg(const int* __restrict__ src, const int* __restrict__ dst,
                      float* __restrict__ out) {
    long long t = (long long)blockIdx.x * blockDim.x + threadIdx.x;
    int e = (int)(t >> 5);
    if (e >= NE) return;
    int lane = threadIdx.x & 31;
    int s = __ldg(src + e);
    int d = __ldg(dst + e);
    int h = lane >> 2;   // cols 4*lane..4*lane+3 all belong to head lane/4
    float a = __ldg(g_ex + (size_t)e * 8 + h) / __ldg(g_denom + d * 8 + h);
    float4 hv = __ldg((const float4*)g_hf + (size_t)s * 32 + lane);
    float4 v = make_float4(a * hv.x, a * hv.y, a * hv.z, a * hv.w);
    red4(out + (size_t)d * 128 + lane * 4, v);
}

extern "C" void kernel_launch(void* const* d_in, const int* in_sizes, int n_in,
                              void* d_out, int out_size) {
    const float* nfeat  = (const float*)d_in[0];
    const float* efeat  = (const float*)d_in[1];
    const int*   src    = (const int*)d_in[2];
    const int*   dst    = (const int*)d_in[3];
    const float* W_fc   = (const float*)d_in[4];
    const float* attn_l = (const float*)d_in[5];
    const float* attn_r = (const float*)d_in[6];
    const float* bias   = (const float*)d_in[7];
    const float* W_e    = (const float*)d_in[8];
    const float* b_e    = (const float*)d_in[9];
    float* out = (float*)d_out;

    k_init<<<4096, 256>>>(bias, out);
    k_ssum<<<(NE * 32 + 255) / 256, 256>>>(efeat, dst);
    k_gemm<0><<<(NN + 31) / 32, 128>>>(nfeat, W_fc, attn_l, attn_r, b_e, out);
    k_score<<<(NE * 2 + 255) / 256, 256>>>(src, dst);
    k_agg<<<(NE * 32 + 255) / 256, 256>>>(src, dst, out);
    k_gemm<1><<<(NN + 31) / 32, 128>>>(nullptr, W_e, attn_l, attn_r, b_e, out);
}

// round 3
// speedup vs baseline: 1.1079x; 1.1079x over previous
#include <cuda_runtime.h>
#include <cuda_bf16.h>

#define NN 50000
#define NE 800000

// ---- device scratch (static: no allocation allowed) ----
__device__ float g_hf[(size_t)NN * 128];     // nfeat @ W_fc
__device__ float g_ssum[(size_t)NN * 128];   // segment_sum(efeat, dst)
__device__ float g_el[NN * 8];
__device__ float g_er[NN * 8];
__device__ int   g_cnt[NN];                  // in-degree
__device__ int   g_off[NN + 1];              // CSR offsets
__device__ int   g_cur[NN];                  // scatter cursors
__device__ int2  g_csr[NE];                  // (src, edge_id) sorted by dst

// ---- zero histogram ----
__global__ void k_zero() {
    int i = blockIdx.x * blockDim.x + threadIdx.x;
    if (i < NN) g_cnt[i] = 0;
}

// ---- histogram of dst ----
__global__ void k_hist(const int* __restrict__ dst) {
    int e = blockIdx.x * blockDim.x + threadIdx.x;
    if (e < NE) atomicAdd(&g_cnt[__ldg(dst + e)], 1);
}

// ---- single-block exclusive scan of g_cnt -> g_off, g_cur ----
__global__ void k_scan() {
    __shared__ int wsum[32];
    __shared__ int carry_s;
    int tid = threadIdx.x;
    if (tid == 0) carry_s = 0;
    __syncthreads();
    for (int base = 0; base < NN; base += 1024) {
        int i = base + tid;
        int v = (i < NN) ? g_cnt[i] : 0;
        int x = v;
#pragma unroll
        for (int o = 1; o < 32; o <<= 1) {
            int y = __shfl_up_sync(0xffffffffu, x, o);
            if ((tid & 31) >= o) x += y;
        }
        if ((tid & 31) == 31) wsum[tid >> 5] = x;
        __syncthreads();
        if (tid < 32) {
            int w = wsum[tid];
#pragma unroll
            for (int o = 1; o < 32; o <<= 1) {
                int y = __shfl_up_sync(0xffffffffu, w, o);
                if (tid >= o) w += y;
            }
            wsum[tid] = w;
        }
        __syncthreads();
        int excl = x - v + ((tid >= 32) ? wsum[(tid >> 5) - 1] : 0) + carry_s;
        if (i < NN) { g_off[i] = excl; g_cur[i] = excl; }
        __syncthreads();
        if (tid == 0) carry_s += wsum[31];
        __syncthreads();
    }
    if (tid == 0) g_off[NN] = carry_s;
}

// ---- scatter edges into CSR buckets ----
__global__ void k_scatter(const int* __restrict__ src, const int* __restrict__ dst) {
    int e = blockIdx.x * blockDim.x + threadIdx.x;
    if (e >= NE) return;
    int d = __ldg(dst + e);
    int pos = atomicAdd(&g_cur[d], 1);
    g_csr[pos] = make_int2(__ldg(src + e), e);
}

// ---- GEMM [rows,128] @ [128,128], fused epilogues ----
// MODE 0: A = nfeat, W = W_fc  -> g_hf, g_el, g_er
// MODE 1: A = g_ssum, W = W_e  -> out += he/max(deg,1) + b_e*(deg>0) + hf/(deg+1)
template <int MODE>
__global__ void __launch_bounds__(128)
k_gemm(const float* __restrict__ A, const float* __restrict__ W,
       const float* __restrict__ attn_l, const float* __restrict__ attn_r,
       const float* __restrict__ b_e, float* __restrict__ out) {
    __shared__ float4 rows4[32 * 32];   // 32 rows x 128 floats
    int col = threadIdx.x;              // 0..127 output column
    int row0 = blockIdx.x * 32;
    int nrows = NN - row0; if (nrows > 32) nrows = 32;

    const float* Ap = (MODE == 1) ? (const float*)g_ssum : A;
    const float4* A4 = (const float4*)Ap + (size_t)row0 * 32;
    for (int i = col; i < 32 * 32; i += 128)
        rows4[i] = (i < nrows * 32) ? __ldg(A4 + i) : make_float4(0.f, 0.f, 0.f, 0.f);
    __syncthreads();

    float acc[32];
#pragma unroll
    for (int r = 0; r < 32; r++) acc[r] = 0.f;

#pragma unroll 1
    for (int kt = 0; kt < 8; kt++) {
        float w[16];
#pragma unroll
        for (int i = 0; i < 16; i++) w[i] = __ldg(W + (kt * 16 + i) * 128 + col);
#pragma unroll
        for (int r = 0; r < 32; r++) {
            float4 v0 = rows4[r * 32 + kt * 4 + 0];
            float4 v1 = rows4[r * 32 + kt * 4 + 1];
            float4 v2 = rows4[r * 32 + kt * 4 + 2];
            float4 v3 = rows4[r * 32 + kt * 4 + 3];
            acc[r] += v0.x * w[0] + v0.y * w[1] + v0.z * w[2] + v0.w * w[3]
                    + v1.x * w[4] + v1.y * w[5] + v1.z * w[6] + v1.w * w[7]
                    + v2.x * w[8] + v2.y * w[9] + v2.z * w[10] + v2.w * w[11]
                    + v3.x * w[12] + v3.y * w[13] + v3.z * w[14] + v3.w * w[15];
        }
    }

    if (MODE == 0) {
        float al = __ldg(attn_l + col);
        float ar = __ldg(attn_r + col);
        for (int r = 0; r < nrows; r++) {
            int n = row0 + r;
            g_hf[(size_t)n * 128 + col] = acc[r];
            float l = acc[r] * al;
            float rr = acc[r] * ar;
#pragma unroll
            for (int o = 8; o; o >>= 1) {
                l += __shfl_down_sync(0xffffffffu, l, o, 16);
                rr += __shfl_down_sync(0xffffffffu, rr, o, 16);
            }
            if ((col & 15) == 0) {
                g_el[n * 8 + (col >> 4)] = l;
                g_er[n * 8 + (col >> 4)] = rr;
            }
        }
    } else {
        float be = __ldg(b_e + col);
        for (int r = 0; r < nrows; r++) {
            int n = row0 + r;
            float deg = (float)g_cnt[n];
            float val = out[(size_t)n * 128 + col];
            val += acc[r] / fmaxf(deg, 1.f);          // (segsum(efeat)@W_e)/max(deg,1)
            val += (deg > 0.f) ? be : 0.f;            // b_e * deg/max(deg,1)
            val += g_hf[(size_t)n * 128 + col] / (deg + 1.f);  // skip term
            out[(size_t)n * 128 + col] = val;
        }
    }
}

// ---- fused per-node pass: softmax-weighted aggregation + efeat segment sum ----
// warp per dst node. out = bias + sum(ex*h[src])/sum(ex); g_ssum = sum(efeat).
__global__ void __launch_bounds__(256)
k_node(const float* __restrict__ efeat, const float* __restrict__ bias,
       float* __restrict__ out) {
    int warp = (blockIdx.x * blockDim.x + threadIdx.x) >> 5;
    if (warp >= NN) return;
    int lane = threadIdx.x & 31;
    int n = warp;
    int beg = g_off[n];
    int end = g_off[n + 1];
    int h = lane >> 2;                       // head owning cols 4*lane..4*lane+3
    float er_h = __ldg(g_er + n * 8 + h);

    float4 acc = make_float4(0.f, 0.f, 0.f, 0.f);
    float4 ss  = make_float4(0.f, 0.f, 0.f, 0.f);
    float denom = 0.f;

    for (int j = beg; j < end; j++) {
        int2 se = __ldg(g_csr + j);
        int s = se.x, e = se.y;
        float v = __ldg(g_el + s * 8 + h) + er_h;
        v = v > 0.f ? v : 0.2f * v;
        float ex = __expf(v);
        denom += ex;
        float4 hv = __ldg((const float4*)g_hf + (size_t)s * 32 + lane);
        float4 ev = __ldg((const float4*)efeat + (size_t)e * 32 + lane);
        acc.x += ex * hv.x; acc.y += ex * hv.y; acc.z += ex * hv.z; acc.w += ex * hv.w;
        ss.x  += ev.x;      ss.y  += ev.y;      ss.z  += ev.z;      ss.w  += ev.w;
    }

    float inv = (denom > 0.f) ? (1.f / denom) : 0.f;
    float4 b4 = __ldg((const float4*)bias + lane);
    float4 o;
    o.x = b4.x + acc.x * inv;
    o.y = b4.y + acc.y * inv;
    o.z = b4.z + acc.z * inv;
    o.w = b4.w + acc.w * inv;
    ((float4*)out)[(size_t)n * 32 + lane] = o;
    ((float4*)g_ssum)[(size_t)n * 32 + lane] = ss;
}

extern "C" void kernel_launch(void* const* d_in, const int* in_sizes, int n_in,
                              void* d_out, int out_size) {
    const float* nfeat  = (const float*)d_in[0];
    const float* efeat  = (const float*)d_in[1];
    const int*   src    = (const int*)d_in[2];
    const int*   dst    = (const int*)d_in[3];
    const float* W_fc   = (const float*)d_in[4];
    const float* attn_l = (const float*)d_in[5];
    const float* attn_r = (const float*)d_in[6];
    const float* bias   = (const float*)d_in[7];
    const float* W_e    = (const float*)d_in[8];
    const float* b_e    = (const float*)d_in[9];
    float* out = (float*)d_out;

    k_zero<<<(NN + 255) / 256, 256>>>();
    k_hist<<<(NE + 255) / 256, 256>>>(dst);
    k_scan<<<1, 1024>>>();
    k_scatter<<<(NE + 255) / 256, 256>>>(src, dst);
    k_gemm<0><<<(NN + 31) / 32, 128>>>(nfeat, W_fc, attn_l, attn_r, b_e, out);
    k_node<<<(NN * 32 + 255) / 256, 256>>>(efeat, bias, out);
    k_gemm<1><<<(NN + 31) / 32, 128>>>(nullptr, W_e, attn_l, attn_r, b_e, out);
}

// round 7
// speedup vs baseline: 1.1256x; 1.0159x over previous
#include <cuda_runtime.h>
#include <cuda_bf16.h>

#define NN 50000
#define NE 800000

// ---- device scratch (static: no allocation allowed) ----
__device__ float g_hf[(size_t)NN * 128];     // nfeat @ W_fc
__device__ float g_ssum[(size_t)NN * 128];   // segment_sum(efeat, dst)
__device__ float g_el[NN * 8];
__device__ float g_er[NN * 8];
__device__ int   g_cnt[NN];                  // in-degree
__device__ int   g_off[NN + 1];              // CSR offsets
__device__ int   g_cur[NN];                  // scatter cursors
__device__ int2  g_csr[NE];                  // (src, edge_id) sorted by dst

// ---- zero histogram ----
__global__ void k_zero() {
    int i = blockIdx.x * blockDim.x + threadIdx.x;
    if (i < NN) g_cnt[i] = 0;
}

// ---- histogram of dst ----
__global__ void k_hist(const int* __restrict__ dst) {
    int e = blockIdx.x * blockDim.x + threadIdx.x;
    if (e < NE) atomicAdd(&g_cnt[__ldg(dst + e)], 1);
}

// ---- single-block exclusive scan of g_cnt -> g_off, g_cur ----
__global__ void k_scan() {
    __shared__ int wsum[32];
    __shared__ int carry_s;
    int tid = threadIdx.x;
    if (tid == 0) carry_s = 0;
    __syncthreads();
    for (int base = 0; base < NN; base += 1024) {
        int i = base + tid;
        int v = (i < NN) ? g_cnt[i] : 0;
        int x = v;
#pragma unroll
        for (int o = 1; o < 32; o <<= 1) {
            int y = __shfl_up_sync(0xffffffffu, x, o);
            if ((tid & 31) >= o) x += y;
        }
        if ((tid & 31) == 31) wsum[tid >> 5] = x;
        __syncthreads();
        if (tid < 32) {
            int w = wsum[tid];
#pragma unroll
            for (int o = 1; o < 32; o <<= 1) {
                int y = __shfl_up_sync(0xffffffffu, w, o);
                if (tid >= o) w += y;
            }
            wsum[tid] = w;
        }
        __syncthreads();
        int excl = x - v + ((tid >= 32) ? wsum[(tid >> 5) - 1] : 0) + carry_s;
        if (i < NN) { g_off[i] = excl; g_cur[i] = excl; }
        __syncthreads();
        if (tid == 0) carry_s += wsum[31];
        __syncthreads();
    }
    if (tid == 0) g_off[NN] = carry_s;
}

// ---- scatter edges into CSR buckets ----
__global__ void k_scatter(const int* __restrict__ src, const int* __restrict__ dst) {
    int e = blockIdx.x * blockDim.x + threadIdx.x;
    if (e >= NE) return;
    int d = __ldg(dst + e);
    int pos = atomicAdd(&g_cur[d], 1);
    g_csr[pos] = make_int2(__ldg(src + e), e);
}

// ---- GEMM [rows,128] @ [128,128], fused epilogues ----
template <int MODE>
__global__ void __launch_bounds__(128)
k_gemm(const float* __restrict__ A, const float* __restrict__ W,
       const float* __restrict__ attn_l, const float* __restrict__ attn_r,
       const float* __restrict__ b_e, float* __restrict__ out) {
    __shared__ float4 rows4[32 * 32];   // 32 rows x 128 floats
    int col = threadIdx.x;              // 0..127 output column
    int row0 = blockIdx.x * 32;
    int nrows = NN - row0; if (nrows > 32) nrows = 32;

    const float* Ap = (MODE == 1) ? (const float*)g_ssum : A;
    const float4* A4 = (const float4*)Ap + (size_t)row0 * 32;
    for (int i = col; i < 32 * 32; i += 128)
        rows4[i] = (i < nrows * 32) ? __ldg(A4 + i) : make_float4(0.f, 0.f, 0.f, 0.f);
    __syncthreads();

    float acc[32];
#pragma unroll
    for (int r = 0; r < 32; r++) acc[r] = 0.f;

#pragma unroll 1
    for (int kt = 0; kt < 8; kt++) {
        float w[16];
#pragma unroll
        for (int i = 0; i < 16; i++) w[i] = __ldg(W + (kt * 16 + i) * 128 + col);
#pragma unroll
        for (int r = 0; r < 32; r++) {
            float4 v0 = rows4[r * 32 + kt * 4 + 0];
            float4 v1 = rows4[r * 32 + kt * 4 + 1];
            float4 v2 = rows4[r * 32 + kt * 4 + 2];
            float4 v3 = rows4[r * 32 + kt * 4 + 3];
            acc[r] += v0.x * w[0] + v0.y * w[1] + v0.z * w[2] + v0.w * w[3]
                    + v1.x * w[4] + v1.y * w[5] + v1.z * w[6] + v1.w * w[7]
                    + v2.x * w[8] + v2.y * w[9] + v2.z * w[10] + v2.w * w[11]
                    + v3.x * w[12] + v3.y * w[13] + v3.z * w[14] + v3.w * w[15];
        }
    }

    if (MODE == 0) {
        float al = __ldg(attn_l + col);
        float ar = __ldg(attn_r + col);
        for (int r = 0; r < nrows; r++) {
            int n = row0 + r;
            g_hf[(size_t)n * 128 + col] = acc[r];
            float l = acc[r] * al;
            float rr = acc[r] * ar;
#pragma unroll
            for (int o = 8; o; o >>= 1) {
                l += __shfl_down_sync(0xffffffffu, l, o, 16);
                rr += __shfl_down_sync(0xffffffffu, rr, o, 16);
            }
            if ((col & 15) == 0) {
                g_el[n * 8 + (col >> 4)] = l;
                g_er[n * 8 + (col >> 4)] = rr;
            }
        }
    } else {
        float be = __ldg(b_e + col);
        for (int r = 0; r < nrows; r++) {
            int n = row0 + r;
            float deg = (float)g_cnt[n];
            float val = out[(size_t)n * 128 + col];
            val += acc[r] / fmaxf(deg, 1.f);
            val += (deg > 0.f) ? be : 0.f;
            val += g_hf[(size_t)n * 128 + col] / (deg + 1.f);
            out[(size_t)n * 128 + col] = val;
        }
    }
}

// ---- fused per-node pass, 4-wide software pipelined ----
// warp per dst node. out = bias + sum(ex*h[src])/sum(ex); g_ssum = sum(efeat).
__global__ void __launch_bounds__(256)
k_node(const float* __restrict__ efeat, const float* __restrict__ bias,
       float* __restrict__ out) {
    int warp = (blockIdx.x * blockDim.x + threadIdx.x) >> 5;
    if (warp >= NN) return;
    int lane = threadIdx.x & 31;
    int n = warp;
    int beg = __ldg(g_off + n);
    int end = __ldg(g_off + n + 1);
    int h = lane >> 2;                       // head owning cols 4*lane..4*lane+3
    float er_h = __ldg(g_er + n * 8 + h);

    float4 acc = make_float4(0.f, 0.f, 0.f, 0.f);
    float4 ss  = make_float4(0.f, 0.f, 0.f, 0.f);
    float denom = 0.f;

    const float4* hf4 = (const float4*)g_hf;
    const float4* ef4 = (const float4*)efeat;

    for (int base = beg; base < end; base += 32) {
        int m = end - base; if (m > 32) m = 32;
        // batch-load up to 32 CSR entries, one per lane (coalesced)
        int2 se = (lane < m) ? __ldg(g_csr + base + lane) : make_int2(0, 0);

        int k = 0;
        for (; k + 4 <= m; k += 4) {
            // distribute indices (register traffic only)
            int s0 = __shfl_sync(0xffffffffu, se.x, k + 0);
            int e0 = __shfl_sync(0xffffffffu, se.y, k + 0);
            int s1 = __shfl_sync(0xffffffffu, se.x, k + 1);
            int e1 = __shfl_sync(0xffffffffu, se.y, k + 1);
            int s2 = __shfl_sync(0xffffffffu, se.x, k + 2);
            int e2 = __shfl_sync(0xffffffffu, se.y, k + 2);
            int s3 = __shfl_sync(0xffffffffu, se.x, k + 3);
            int e3 = __shfl_sync(0xffffffffu, se.y, k + 3);
            // issue all 12 loads before any consumption
            float l0 = __ldg(g_el + s0 * 8 + h);
            float l1 = __ldg(g_el + s1 * 8 + h);
            float l2 = __ldg(g_el + s2 * 8 + h);
            float l3 = __ldg(g_el + s3 * 8 + h);
            float4 hv0 = __ldg(hf4 + (size_t)s0 * 32 + lane);
            float4 hv1 = __ldg(hf4 + (size_t)s1 * 32 + lane);
            float4 hv2 = __ldg(hf4 + (size_t)s2 * 32 + lane);
            float4 hv3 = __ldg(hf4 + (size_t)s3 * 32 + lane);
            float4 ev0 = __ldg(ef4 + (size_t)e0 * 32 + lane);
            float4 ev1 = __ldg(ef4 + (size_t)e1 * 32 + lane);
            float4 ev2 = __ldg(ef4 + (size_t)e2 * 32 + lane);
            float4 ev3 = __ldg(ef4 + (size_t)e3 * 32 + lane);

            float v, ex;
            v = l0 + er_h; v = v > 0.f ? v : 0.2f * v; ex = __expf(v);
            denom += ex;
            acc.x += ex * hv0.x; acc.y += ex * hv0.y; acc.z += ex * hv0.z; acc.w += ex * hv0.w;
            v = l1 + er_h; v = v > 0.f ? v : 0.2f * v; ex = __expf(v);
            denom += ex;
            acc.x += ex * hv1.x; acc.y += ex * hv1.y; acc.z += ex * hv1.z; acc.w += ex * hv1.w;
            v = l2 + er_h; v = v > 0.f ? v : 0.2f * v; ex = __expf(v);
            denom += ex;
            acc.x += ex * hv2.x; acc.y += ex * hv2.y; acc.z += ex * hv2.z; acc.w += ex * hv2.w;
            v = l3 + er_h; v = v > 0.f ? v : 0.2f * v; ex = __expf(v);
            denom += ex;
            acc.x += ex * hv3.x; acc.y += ex * hv3.y; acc.z += ex * hv3.z; acc.w += ex * hv3.w;

            ss.x += ev0.x + ev1.x + ev2.x + ev3.x;
            ss.y += ev0.y + ev1.y + ev2.y + ev3.y;
            ss.z += ev0.z + ev1.z + ev2.z + ev3.z;
            ss.w += ev0.w + ev1.w + ev2.w + ev3.w;
        }
        for (; k < m; k++) {
            int s = __shfl_sync(0xffffffffu, se.x, k);
            int e = __shfl_sync(0xffffffffu, se.y, k);
            float v = __ldg(g_el + s * 8 + h) + er_h;
            v = v > 0.f ? v : 0.2f * v;
            float ex = __expf(v);
            denom += ex;
            float4 hv = __ldg(hf4 + (size_t)s * 32 + lane);
            float4 ev = __ldg(ef4 + (size_t)e * 32 + lane);
            acc.x += ex * hv.x; acc.y += ex * hv.y; acc.z += ex * hv.z; acc.w += ex * hv.w;
            ss.x += ev.x; ss.y += ev.y; ss.z += ev.z; ss.w += ev.w;
        }
    }

    float inv = (denom > 0.f) ? (1.f / denom) : 0.f;
    float4 b4 = __ldg((const float4*)bias + lane);
    float4 o;
    o.x = b4.x + acc.x * inv;
    o.y = b4.y + acc.y * inv;
    o.z = b4.z + acc.z * inv;
    o.w = b4.w + acc.w * inv;
    ((float4*)out)[(size_t)n * 32 + lane] = o;
    ((float4*)g_ssum)[(size_t)n * 32 + lane] = ss;
}

extern "C" void kernel_launch(void* const* d_in, const int* in_sizes, int n_in,
                              void* d_out, int out_size) {
    const float* nfeat  = (const float*)d_in[0];
    const float* efeat  = (const float*)d_in[1];
    const int*   src    = (const int*)d_in[2];
    const int*   dst    = (const int*)d_in[3];
    const float* W_fc   = (const float*)d_in[4];
    const float* attn_l = (const float*)d_in[5];
    const float* attn_r = (const float*)d_in[6];
    const float* bias   = (const float*)d_in[7];
    const float* W_e    = (const float*)d_in[8];
    const float* b_e    = (const float*)d_in[9];
    float* out = (float*)d_out;

    k_zero<<<(NN + 255) / 256, 256>>>();
    k_hist<<<(NE + 255) / 256, 256>>>(dst);
    k_scan<<<1, 1024>>>();
    k_scatter<<<(NE + 255) / 256, 256>>>(src, dst);
    k_gemm<0><<<(NN + 31) / 32, 128>>>(nfeat, W_fc, attn_l, attn_r, b_e, out);
    k_node<<<(NN * 32 + 255) / 256, 256>>>(efeat, bias, out);
    k_gemm<1><<<(NN + 31) / 32, 128>>>(nullptr, W_e, attn_l, attn_r, b_e, out);
}

// round 8
// speedup vs baseline: 1.3697x; 1.2169x over previous
#include <cuda_runtime.h>
#include <cuda_bf16.h>

#define NN 50000
#define NE 800000

// ---- device scratch (static: no allocation allowed) ----
__device__ float g_hf[(size_t)NN * 128];     // nfeat @ W_fc
__device__ float g_ssum[(size_t)NN * 128];   // segment_sum(efeat, dst)
__device__ float g_el[NN * 8];
__device__ float g_er[NN * 8];
__device__ int   g_cnt[NN];                  // in-degree
__device__ int   g_off[NN + 1];              // CSR offsets
__device__ int   g_cur[NN];                  // scatter cursors
__device__ int2  g_csr[NE];                  // (src, edge_id) sorted by dst

__device__ __forceinline__ float f2lo(unsigned long long v) {
    return __uint_as_float((unsigned)v);
}
__device__ __forceinline__ float f2hi(unsigned long long v) {
    return __uint_as_float((unsigned)(v >> 32));
}

// ---- zero histogram ----
__global__ void k_zero() {
    int i = blockIdx.x * blockDim.x + threadIdx.x;
    if (i < NN) g_cnt[i] = 0;
}

// ---- histogram of dst ----
__global__ void k_hist(const int* __restrict__ dst) {
    int e = blockIdx.x * blockDim.x + threadIdx.x;
    if (e < NE) atomicAdd(&g_cnt[__ldg(dst + e)], 1);
}

// ---- single-block exclusive scan of g_cnt -> g_off, g_cur ----
__global__ void k_scan() {
    __shared__ int wsum[32];
    __shared__ int carry_s;
    int tid = threadIdx.x;
    if (tid == 0) carry_s = 0;
    __syncthreads();
    for (int base = 0; base < NN; base += 1024) {
        int i = base + tid;
        int v = (i < NN) ? g_cnt[i] : 0;
        int x = v;
#pragma unroll
        for (int o = 1; o < 32; o <<= 1) {
            int y = __shfl_up_sync(0xffffffffu, x, o);
            if ((tid & 31) >= o) x += y;
        }
        if ((tid & 31) == 31) wsum[tid >> 5] = x;
        __syncthreads();
        if (tid < 32) {
            int w = wsum[tid];
#pragma unroll
            for (int o = 1; o < 32; o <<= 1) {
                int y = __shfl_up_sync(0xffffffffu, w, o);
                if (tid >= o) w += y;
            }
            wsum[tid] = w;
        }
        __syncthreads();
        int excl = x - v + ((tid >= 32) ? wsum[(tid >> 5) - 1] : 0) + carry_s;
        if (i < NN) { g_off[i] = excl; g_cur[i] = excl; }
        __syncthreads();
        if (tid == 0) carry_s += wsum[31];
        __syncthreads();
    }
    if (tid == 0) g_off[NN] = carry_s;
}

// ---- scatter edges into CSR buckets ----
__global__ void k_scatter(const int* __restrict__ src, const int* __restrict__ dst) {
    int e = blockIdx.x * blockDim.x + threadIdx.x;
    if (e >= NE) return;
    int d = __ldg(dst + e);
    int pos = atomicAdd(&g_cur[d], 1);
    g_csr[pos] = make_int2(__ldg(src + e), e);
}

// ---- GEMM [128 rows x 128 cols] per block, f32x2 packed FMA ----
// MODE 0: A = nfeat, W = W_fc  -> g_hf, g_el, g_er
// MODE 1: A = g_ssum, W = W_e  -> out += he/max(deg,1) + b_e*(deg>0) + hf/(deg+1)
// smem: sA = float2[64 rowpairs][128 k] (64KB), sW = float[128 k][128 c] (64KB)
template <int MODE>
__global__ void __launch_bounds__(256)
k_gemm2(const float* __restrict__ A, const float* __restrict__ W,
        const float* __restrict__ attn_l, const float* __restrict__ attn_r,
        const float* __restrict__ b_e, float* __restrict__ out) {
    extern __shared__ float smem[];
    float2* sA = (float2*)smem;          // sA[p*128 + k] = (row2p[k], row2p+1[k])
    float*  sW = smem + 16384;           // sW[k*128 + c]
    int t = threadIdx.x;
    int row0 = blockIdx.x * 128;
    int nrows = NN - row0; if (nrows > 128) nrows = 128;
    const float* Ap = (MODE == 1) ? (const float*)g_ssum : A;

    // stage W (64KB, coalesced)
    {
        const float4* W4 = (const float4*)W;
        float4* sW4 = (float4*)sW;
#pragma unroll
        for (int i = t; i < 4096; i += 256) sW4[i] = __ldg(W4 + i);
    }
    // stage A row-pair interleaved
    {
        const float4* A4 = (const float4*)Ap + (size_t)row0 * 32;
        for (int i = t; i < 2048; i += 256) {
            int p = i >> 5, kq = i & 31;
            float4 a0 = (2 * p < nrows) ? __ldg(A4 + (size_t)(2 * p) * 32 + kq)
                                        : make_float4(0.f, 0.f, 0.f, 0.f);
            float4 a1 = (2 * p + 1 < nrows) ? __ldg(A4 + (size_t)(2 * p + 1) * 32 + kq)
                                            : make_float4(0.f, 0.f, 0.f, 0.f);
            float2* d2 = sA + p * 128 + kq * 4;
            d2[0] = make_float2(a0.x, a1.x);
            d2[1] = make_float2(a0.y, a1.y);
            d2[2] = make_float2(a0.z, a1.z);
            d2[3] = make_float2(a0.w, a1.w);
        }
    }
    __syncthreads();

    int lane = t & 31;   // cols 4*lane .. 4*lane+3
    int wrp  = t >> 5;   // rowpairs 8*wrp .. 8*wrp+7  (rows 16*wrp .. +15)
    int c0 = lane * 4;
    const unsigned long long* sA64 =
        (const unsigned long long*)(sA + wrp * 8 * 128);

    unsigned long long acc[8][4];
#pragma unroll
    for (int j = 0; j < 8; j++)
#pragma unroll
        for (int q = 0; q < 4; q++) acc[j][q] = 0ull;

#pragma unroll 4
    for (int k = 0; k < 128; k++) {
        float4 w4 = *(const float4*)(sW + k * 128 + c0);
        unsigned long long w2[4];
        {
            unsigned wx = __float_as_uint(w4.x), wy = __float_as_uint(w4.y);
            unsigned wz = __float_as_uint(w4.z), ww = __float_as_uint(w4.w);
            asm("mov.b64 %0, {%1,%1};" : "=l"(w2[0]) : "r"(wx));
            asm("mov.b64 %0, {%1,%1};" : "=l"(w2[1]) : "r"(wy));
            asm("mov.b64 %0, {%1,%1};" : "=l"(w2[2]) : "r"(wz));
            asm("mov.b64 %0, {%1,%1};" : "=l"(w2[3]) : "r"(ww));
        }
#pragma unroll
        for (int j = 0; j < 8; j++) {
            unsigned long long a2 = sA64[j * 128 + k];   // warp-broadcast LDS.64
            asm("fma.rn.f32x2 %0, %1, %2, %0;" : "+l"(acc[j][0]) : "l"(a2), "l"(w2[0]));
            asm("fma.rn.f32x2 %0, %1, %2, %0;" : "+l"(acc[j][1]) : "l"(a2), "l"(w2[1]));
            asm("fma.rn.f32x2 %0, %1, %2, %0;" : "+l"(acc[j][2]) : "l"(a2), "l"(w2[2]));
            asm("fma.rn.f32x2 %0, %1, %2, %0;" : "+l"(acc[j][3]) : "l"(a2), "l"(w2[3]));
        }
    }

    if (MODE == 0) {
        float4 al4 = __ldg((const float4*)attn_l + lane);
        float4 ar4 = __ldg((const float4*)attn_r + lane);
#pragma unroll
        for (int j = 0; j < 8; j++) {
            int re = row0 + wrp * 16 + 2 * j;
#pragma unroll
            for (int half = 0; half < 2; half++) {
                int n = re + half;
                if (n >= NN) continue;
                float4 v;
                if (half == 0)
                    v = make_float4(f2lo(acc[j][0]), f2lo(acc[j][1]),
                                    f2lo(acc[j][2]), f2lo(acc[j][3]));
                else
                    v = make_float4(f2hi(acc[j][0]), f2hi(acc[j][1]),
                                    f2hi(acc[j][2]), f2hi(acc[j][3]));
                ((float4*)g_hf)[(size_t)n * 32 + lane] = v;
                float l = v.x * al4.x + v.y * al4.y + v.z * al4.z + v.w * al4.w;
                float r = v.x * ar4.x + v.y * ar4.y + v.z * ar4.z + v.w * ar4.w;
                l += __shfl_down_sync(0xffffffffu, l, 1, 4);
                l += __shfl_down_sync(0xffffffffu, l, 2, 4);
                r += __shfl_down_sync(0xffffffffu, r, 1, 4);
                r += __shfl_down_sync(0xffffffffu, r, 2, 4);
                if ((lane & 3) == 0) {
                    g_el[n * 8 + (lane >> 2)] = l;
                    g_er[n * 8 + (lane >> 2)] = r;
                }
            }
        }
    } else {
        float4 be4 = __ldg((const float4*)b_e + lane);
#pragma unroll
        for (int j = 0; j < 8; j++) {
            int re = row0 + wrp * 16 + 2 * j;
#pragma unroll
            for (int half = 0; half < 2; half++) {
                int n = re + half;
                if (n >= NN) continue;
                float4 v;
                if (half == 0)
                    v = make_float4(f2lo(acc[j][0]), f2lo(acc[j][1]),
                                    f2lo(acc[j][2]), f2lo(acc[j][3]));
                else
                    v = make_float4(f2hi(acc[j][0]), f2hi(acc[j][1]),
                                    f2hi(acc[j][2]), f2hi(acc[j][3]));
                float deg = (float)__ldg(g_cnt + n);
                float invd = 1.f / fmaxf(deg, 1.f);
                float invp = 1.f / (deg + 1.f);
                float bs = (deg > 0.f) ? 1.f : 0.f;
                float4 o4 = ((float4*)out)[(size_t)n * 32 + lane];
                float4 h4 = ((const float4*)g_hf)[(size_t)n * 32 + lane];
                o4.x += v.x * invd + be4.x * bs + h4.x * invp;
                o4.y += v.y * invd + be4.y * bs + h4.y * invp;
                o4.z += v.z * invd + be4.z * bs + h4.z * invp;
                o4.w += v.w * invd + be4.w * bs + h4.w * invp;
                ((float4*)out)[(size_t)n * 32 + lane] = o4;
            }
        }
    }
}

// ---- fused per-node pass, 4-wide software pipelined ----
// warp per dst node. out = bias + sum(ex*h[src])/sum(ex); g_ssum = sum(efeat).
__global__ void __launch_bounds__(256)
k_node(const float* __restrict__ efeat, const float* __restrict__ bias,
       float* __restrict__ out) {
    int warp = (blockIdx.x * blockDim.x + threadIdx.x) >> 5;
    if (warp >= NN) return;
    int lane = threadIdx.x & 31;
    int n = warp;
    int beg = __ldg(g_off + n);
    int end = __ldg(g_off + n + 1);
    int h = lane >> 2;
    float er_h = __ldg(g_er + n * 8 + h);

    float4 acc = make_float4(0.f, 0.f, 0.f, 0.f);
    float4 ss  = make_float4(0.f, 0.f, 0.f, 0.f);
    float denom = 0.f;

    const float4* hf4 = (const float4*)g_hf;
    const float4* ef4 = (const float4*)efeat;

    for (int base = beg; base < end; base += 32) {
        int m = end - base; if (m > 32) m = 32;
        int2 se = (lane < m) ? __ldg(g_csr + base + lane) : make_int2(0, 0);

        int k = 0;
        for (; k + 4 <= m; k += 4) {
            int s0 = __shfl_sync(0xffffffffu, se.x, k + 0);
            int e0 = __shfl_sync(0xffffffffu, se.y, k + 0);
            int s1 = __shfl_sync(0xffffffffu, se.x, k + 1);
            int e1 = __shfl_sync(0xffffffffu, se.y, k + 1);
            int s2 = __shfl_sync(0xffffffffu, se.x, k + 2);
            int e2 = __shfl_sync(0xffffffffu, se.y, k + 2);
            int s3 = __shfl_sync(0xffffffffu, se.x, k + 3);
            int e3 = __shfl_sync(0xffffffffu, se.y, k + 3);
            float l0 = __ldg(g_el + s0 * 8 + h);
            float l1 = __ldg(g_el + s1 * 8 + h);
            float l2 = __ldg(g_el + s2 * 8 + h);
            float l3 = __ldg(g_el + s3 * 8 + h);
            float4 hv0 = __ldg(hf4 + (size_t)s0 * 32 + lane);
            float4 hv1 = __ldg(hf4 + (size_t)s1 * 32 + lane);
            float4 hv2 = __ldg(hf4 + (size_t)s2 * 32 + lane);
            float4 hv3 = __ldg(hf4 + (size_t)s3 * 32 + lane);
            float4 ev0 = __ldg(ef4 + (size_t)e0 * 32 + lane);
            float4 ev1 = __ldg(ef4 + (size_t)e1 * 32 + lane);
            float4 ev2 = __ldg(ef4 + (size_t)e2 * 32 + lane);
            float4 ev3 = __ldg(ef4 + (size_t)e3 * 32 + lane);

            float v, ex;
            v = l0 + er_h; v = v > 0.f ? v : 0.2f * v; ex = __expf(v);
            denom += ex;
            acc.x += ex * hv0.x; acc.y += ex * hv0.y; acc.z += ex * hv0.z; acc.w += ex * hv0.w;
            v = l1 + er_h; v = v > 0.f ? v : 0.2f * v; ex = __expf(v);
            denom += ex;
            acc.x += ex * hv1.x; acc.y += ex * hv1.y; acc.z += ex * hv1.z; acc.w += ex * hv1.w;
            v = l2 + er_h; v = v > 0.f ? v : 0.2f * v; ex = __expf(v);
            denom += ex;
            acc.x += ex * hv2.x; acc.y += ex * hv2.y; acc.z += ex * hv2.z; acc.w += ex * hv2.w;
            v = l3 + er_h; v = v > 0.f ? v : 0.2f * v; ex = __expf(v);
            denom += ex;
            acc.x += ex * hv3.x; acc.y += ex * hv3.y; acc.z += ex * hv3.z; acc.w += ex * hv3.w;

            ss.x += ev0.x + ev1.x + ev2.x + ev3.x;
            ss.y += ev0.y + ev1.y + ev2.y + ev3.y;
            ss.z += ev0.z + ev1.z + ev2.z + ev3.z;
            ss.w += ev0.w + ev1.w + ev2.w + ev3.w;
        }
        for (; k < m; k++) {
            int s = __shfl_sync(0xffffffffu, se.x, k);
            int e = __shfl_sync(0xffffffffu, se.y, k);
            float v = __ldg(g_el + s * 8 + h) + er_h;
            v = v > 0.f ? v : 0.2f * v;
            float ex = __expf(v);
            denom += ex;
            float4 hv = __ldg(hf4 + (size_t)s * 32 + lane);
            float4 ev = __ldg(ef4 + (size_t)e * 32 + lane);
            acc.x += ex * hv.x; acc.y += ex * hv.y; acc.z += ex * hv.z; acc.w += ex * hv.w;
            ss.x += ev.x; ss.y += ev.y; ss.z += ev.z; ss.w += ev.w;
        }
    }

    float inv = (denom > 0.f) ? (1.f / denom) : 0.f;
    float4 b4 = __ldg((const float4*)bias + lane);
    float4 o;
    o.x = b4.x + acc.x * inv;
    o.y = b4.y + acc.y * inv;
    o.z = b4.z + acc.z * inv;
    o.w = b4.w + acc.w * inv;
    ((float4*)out)[(size_t)n * 32 + lane] = o;
    ((float4*)g_ssum)[(size_t)n * 32 + lane] = ss;
}

extern "C" void kernel_launch(void* const* d_in, const int* in_sizes, int n_in,
                              void* d_out, int out_size) {
    const float* nfeat  = (const float*)d_in[0];
    const float* efeat  = (const float*)d_in[1];
    const int*   src    = (const int*)d_in[2];
    const int*   dst    = (const int*)d_in[3];
    const float* W_fc   = (const float*)d_in[4];
    const float* attn_l = (const float*)d_in[5];
    const float* attn_r = (const float*)d_in[6];
    const float* bias   = (const float*)d_in[7];
    const float* W_e    = (const float*)d_in[8];
    const float* b_e    = (const float*)d_in[9];
    float* out = (float*)d_out;

    const int SMEM = 131072;  // 64KB sA + 64KB sW
    cudaFuncSetAttribute(k_gemm2<0>, cudaFuncAttributeMaxDynamicSharedMemorySize, SMEM);
    cudaFuncSetAttribute(k_gemm2<1>, cudaFuncAttributeMaxDynamicSharedMemorySize, SMEM);

    k_zero<<<(NN + 255) / 256, 256>>>();
    k_hist<<<(NE + 255) / 256, 256>>>(dst);
    k_scan<<<1, 1024>>>();
    k_scatter<<<(NE + 255) / 256, 256>>>(src, dst);
    k_gemm2<0><<<(NN + 127) / 128, 256, SMEM>>>(nfeat, W_fc, attn_l, attn_r, b_e, out);
    k_node<<<(NN * 32 + 255) / 256, 256>>>(efeat, bias, out);
    k_gemm2<1><<<(NN + 127) / 128, 256, SMEM>>>(nfeat, W_e, attn_l, attn_r, b_e, out);
}

// round 10
// speedup vs baseline: 1.5359x; 1.1213x over previous
#include <cuda_runtime.h>
#include <cuda_bf16.h>

#define NN 50000
#define NE 800000

// ---- device scratch (static: no allocation allowed) ----
__device__ float g_hf[(size_t)NN * 128];     // nfeat @ W_fc
__device__ float g_ssum[(size_t)NN * 128];   // segment_sum(efeat, dst)
__device__ float g_el[NN * 8];
__device__ float g_er[NN * 8];
__device__ int   g_cnt[NN];                  // in-degree
__device__ int   g_off[NN + 1];              // CSR offsets
__device__ int   g_cur[NN];                  // scatter cursors
__device__ int2  g_csr[NE];                  // (src, edge_id) sorted by dst

__device__ __forceinline__ float f2lo(unsigned long long v) {
    return __uint_as_float((unsigned)v);
}
__device__ __forceinline__ float f2hi(unsigned long long v) {
    return __uint_as_float((unsigned)(v >> 32));
}

// ---- zero histogram ----
__global__ void k_zero() {
    int i = blockIdx.x * blockDim.x + threadIdx.x;
    if (i < NN) g_cnt[i] = 0;
}

// ---- histogram of dst ----
__global__ void k_hist(const int* __restrict__ dst) {
    int e = blockIdx.x * blockDim.x + threadIdx.x;
    if (e < NE) atomicAdd(&g_cnt[__ldg(dst + e)], 1);
}

// ---- single-block exclusive scan of g_cnt -> g_off, g_cur ----
__global__ void k_scan() {
    __shared__ int wsum[32];
    __shared__ int carry_s;
    int tid = threadIdx.x;
    if (tid == 0) carry_s = 0;
    __syncthreads();
    for (int base = 0; base < NN; base += 1024) {
        int i = base + tid;
        int v = (i < NN) ? g_cnt[i] : 0;
        int x = v;
#pragma unroll
        for (int o = 1; o < 32; o <<= 1) {
            int y = __shfl_up_sync(0xffffffffu, x, o);
            if ((tid & 31) >= o) x += y;
        }
        if ((tid & 31) == 31) wsum[tid >> 5] = x;
        __syncthreads();
        if (tid < 32) {
            int w = wsum[tid];
#pragma unroll
            for (int o = 1; o < 32; o <<= 1) {
                int y = __shfl_up_sync(0xffffffffu, w, o);
                if (tid >= o) w += y;
            }
            wsum[tid] = w;
        }
        __syncthreads();
        int excl = x - v + ((tid >= 32) ? wsum[(tid >> 5) - 1] : 0) + carry_s;
        if (i < NN) { g_off[i] = excl; g_cur[i] = excl; }
        __syncthreads();
        if (tid == 0) carry_s += wsum[31];
        __syncthreads();
    }
    if (tid == 0) g_off[NN] = carry_s;
}

// ---- scatter edges into CSR buckets ----
__global__ void k_scatter(const int* __restrict__ src, const int* __restrict__ dst) {
    int e = blockIdx.x * blockDim.x + threadIdx.x;
    if (e >= NE) return;
    int d = __ldg(dst + e);
    int pos = atomicAdd(&g_cur[d], 1);
    g_csr[pos] = make_int2(__ldg(src + e), e);
}

// ---- GEMM [128 rows x 128 cols] per block, f32x2 packed FMA ----
template <int MODE>
__global__ void __launch_bounds__(256)
k_gemm2(const float* __restrict__ A, const float* __restrict__ W,
        const float* __restrict__ attn_l, const float* __restrict__ attn_r,
        const float* __restrict__ b_e, float* __restrict__ out) {
    extern __shared__ float smem[];
    float2* sA = (float2*)smem;          // sA[p*128 + k] = (row2p[k], row2p+1[k])
    float*  sW = smem + 16384;           // sW[k*128 + c]
    int t = threadIdx.x;
    int row0 = blockIdx.x * 128;
    int nrows = NN - row0; if (nrows > 128) nrows = 128;
    const float* Ap = (MODE == 1) ? (const float*)g_ssum : A;

    {
        const float4* W4 = (const float4*)W;
        float4* sW4 = (float4*)sW;
#pragma unroll
        for (int i = t; i < 4096; i += 256) sW4[i] = __ldg(W4 + i);
    }
    {
        const float4* A4 = (const float4*)Ap + (size_t)row0 * 32;
        for (int i = t; i < 2048; i += 256) {
            int p = i >> 5, kq = i & 31;
            float4 a0 = (2 * p < nrows) ? __ldg(A4 + (size_t)(2 * p) * 32 + kq)
                                        : make_float4(0.f, 0.f, 0.f, 0.f);
            float4 a1 = (2 * p + 1 < nrows) ? __ldg(A4 + (size_t)(2 * p + 1) * 32 + kq)
                                            : make_float4(0.f, 0.f, 0.f, 0.f);
            float2* d2 = sA + p * 128 + kq * 4;
            d2[0] = make_float2(a0.x, a1.x);
            d2[1] = make_float2(a0.y, a1.y);
            d2[2] = make_float2(a0.z, a1.z);
            d2[3] = make_float2(a0.w, a1.w);
        }
    }
    __syncthreads();

    int lane = t & 31;   // cols 4*lane .. 4*lane+3
    int wrp  = t >> 5;   // rowpairs 8*wrp..+7 (rows 16*wrp..+15)
    int c0 = lane * 4;
    const unsigned long long* sA64 =
        (const unsigned long long*)(sA + wrp * 8 * 128);

    unsigned long long acc[8][4];
#pragma unroll
    for (int j = 0; j < 8; j++)
#pragma unroll
        for (int q = 0; q < 4; q++) acc[j][q] = 0ull;

#pragma unroll 4
    for (int k = 0; k < 128; k++) {
        float4 w4 = *(const float4*)(sW + k * 128 + c0);
        unsigned long long w2[4];
        {
            unsigned wx = __float_as_uint(w4.x), wy = __float_as_uint(w4.y);
            unsigned wz = __float_as_uint(w4.z), ww = __float_as_uint(w4.w);
            asm("mov.b64 %0, {%1,%1};" : "=l"(w2[0]) : "r"(wx));
            asm("mov.b64 %0, {%1,%1};" : "=l"(w2[1]) : "r"(wy));
            asm("mov.b64 %0, {%1,%1};" : "=l"(w2[2]) : "r"(wz));
            asm("mov.b64 %0, {%1,%1};" : "=l"(w2[3]) : "r"(ww));
        }
#pragma unroll
        for (int j = 0; j < 8; j++) {
            unsigned long long a2 = sA64[j * 128 + k];
            asm("fma.rn.f32x2 %0, %1, %2, %0;" : "+l"(acc[j][0]) : "l"(a2), "l"(w2[0]));
            asm("fma.rn.f32x2 %0, %1, %2, %0;" : "+l"(acc[j][1]) : "l"(a2), "l"(w2[1]));
            asm("fma.rn.f32x2 %0, %1, %2, %0;" : "+l"(acc[j][2]) : "l"(a2), "l"(w2[2]));
            asm("fma.rn.f32x2 %0, %1, %2, %0;" : "+l"(acc[j][3]) : "l"(a2), "l"(w2[3]));
        }
    }

    if (MODE == 0) {
        float4 al4 = __ldg((const float4*)attn_l + lane);
        float4 ar4 = __ldg((const float4*)attn_r + lane);
#pragma unroll
        for (int j = 0; j < 8; j++) {
            int re = row0 + wrp * 16 + 2 * j;
#pragma unroll
            for (int half = 0; half < 2; half++) {
                int n = re + half;
                if (n >= NN) continue;
                float4 v;
                if (half == 0)
                    v = make_float4(f2lo(acc[j][0]), f2lo(acc[j][1]),
                                    f2lo(acc[j][2]), f2lo(acc[j][3]));
                else
                    v = make_float4(f2hi(acc[j][0]), f2hi(acc[j][1]),
                                    f2hi(acc[j][2]), f2hi(acc[j][3]));
                ((float4*)g_hf)[(size_t)n * 32 + lane] = v;
                float l = v.x * al4.x + v.y * al4.y + v.z * al4.z + v.w * al4.w;
                float r = v.x * ar4.x + v.y * ar4.y + v.z * ar4.z + v.w * ar4.w;
                l += __shfl_down_sync(0xffffffffu, l, 1, 4);
                l += __shfl_down_sync(0xffffffffu, l, 2, 4);
                r += __shfl_down_sync(0xffffffffu, r, 1, 4);
                r += __shfl_down_sync(0xffffffffu, r, 2, 4);
                if ((lane & 3) == 0) {
                    g_el[n * 8 + (lane >> 2)] = l;
                    g_er[n * 8 + (lane >> 2)] = r;
                }
            }
        }
    } else {
        float4 be4 = __ldg((const float4*)b_e + lane);
#pragma unroll
        for (int j = 0; j < 8; j++) {
            int re = row0 + wrp * 16 + 2 * j;
#pragma unroll
            for (int half = 0; half < 2; half++) {
                int n = re + half;
                if (n >= NN) continue;
                float4 v;
                if (half == 0)
                    v = make_float4(f2lo(acc[j][0]), f2lo(acc[j][1]),
                                    f2lo(acc[j][2]), f2lo(acc[j][3]));
                else
                    v = make_float4(f2hi(acc[j][0]), f2hi(acc[j][1]),
                                    f2hi(acc[j][2]), f2hi(acc[j][3]));
                float deg = (float)__ldg(g_cnt + n);
                float invd = 1.f / fmaxf(deg, 1.f);
                float invp = 1.f / (deg + 1.f);
                float bs = (deg > 0.f) ? 1.f : 0.f;
                float4 o4 = ((float4*)out)[(size_t)n * 32 + lane];
                float4 h4 = ((const float4*)g_hf)[(size_t)n * 32 + lane];
                o4.x += v.x * invd + be4.x * bs + h4.x * invp;
                o4.y += v.y * invd + be4.y * bs + h4.y * invp;
                o4.z += v.z * invd + be4.z * bs + h4.z * invp;
                o4.w += v.w * invd + be4.w * bs + h4.w * invp;
                ((float4*)out)[(size_t)n * 32 + lane] = o4;
            }
        }
    }
}

// ---- efeat segment-sum only (DRAM-bound), warp per node ----
__global__ void __launch_bounds__(256)
k_esum(const float* __restrict__ efeat) {
    int warp = (blockIdx.x * blockDim.x + threadIdx.x) >> 5;
    if (warp >= NN) return;
    int lane = threadIdx.x & 31;
    int beg = __ldg(g_off + warp);
    int end = __ldg(g_off + warp + 1);
    const float4* ef4 = (const float4*)efeat;
    float4 ss = make_float4(0.f, 0.f, 0.f, 0.f);

    for (int base = beg; base < end; base += 32) {
        int m = end - base; if (m > 32) m = 32;
        int eid = (lane < m) ? __ldg(&g_csr[base + lane].y) : 0;
        int k = 0;
        for (; k + 4 <= m; k += 4) {
            int e0 = __shfl_sync(0xffffffffu, eid, k + 0);
            int e1 = __shfl_sync(0xffffffffu, eid, k + 1);
            int e2 = __shfl_sync(0xffffffffu, eid, k + 2);
            int e3 = __shfl_sync(0xffffffffu, eid, k + 3);
            float4 v0 = __ldg(ef4 + (size_t)e0 * 32 + lane);
            float4 v1 = __ldg(ef4 + (size_t)e1 * 32 + lane);
            float4 v2 = __ldg(ef4 + (size_t)e2 * 32 + lane);
            float4 v3 = __ldg(ef4 + (size_t)e3 * 32 + lane);
            ss.x += v0.x + v1.x + v2.x + v3.x;
            ss.y += v0.y + v1.y + v2.y + v3.y;
            ss.z += v0.z + v1.z + v2.z + v3.z;
            ss.w += v0.w + v1.w + v2.w + v3.w;
        }
        for (; k < m; k++) {
            int e = __shfl_sync(0xffffffffu, eid, k);
            float4 v = __ldg(ef4 + (size_t)e * 32 + lane);
            ss.x += v.x; ss.y += v.y; ss.z += v.z; ss.w += v.w;
        }
    }
    ((float4*)g_ssum)[(size_t)warp * 32 + lane] = ss;
}

// ---- attention aggregation only (L2-bound), warp per node ----
__global__ void __launch_bounds__(256)
k_att(const float* __restrict__ bias, float* __restrict__ out) {
    int warp = (blockIdx.x * blockDim.x + threadIdx.x) >> 5;
    if (warp >= NN) return;
    int lane = threadIdx.x & 31;
    int n = warp;
    int beg = __ldg(g_off + n);
    int end = __ldg(g_off + n + 1);
    int h = lane >> 2;
    float er_h = __ldg(g_er + n * 8 + h);

    float4 acc = make_float4(0.f, 0.f, 0.f, 0.f);
    float denom = 0.f;
    const float4* hf4 = (const float4*)g_hf;

    for (int base = beg; base < end; base += 32) {
        int m = end - base; if (m > 32) m = 32;
        int sid = (lane < m) ? __ldg(&g_csr[base + lane].x) : 0;
        int k = 0;
        for (; k + 4 <= m; k += 4) {
            int s0 = __shfl_sync(0xffffffffu, sid, k + 0);
            int s1 = __shfl_sync(0xffffffffu, sid, k + 1);
            int s2 = __shfl_sync(0xffffffffu, sid, k + 2);
            int s3 = __shfl_sync(0xffffffffu, sid, k + 3);
            float l0 = __ldg(g_el + s0 * 8 + h);
            float l1 = __ldg(g_el + s1 * 8 + h);
            float l2 = __ldg(g_el + s2 * 8 + h);
            float l3 = __ldg(g_el + s3 * 8 + h);
            float4 hv0 = __ldg(hf4 + (size_t)s0 * 32 + lane);
            float4 hv1 = __ldg(hf4 + (size_t)s1 * 32 + lane);
            float4 hv2 = __ldg(hf4 + (size_t)s2 * 32 + lane);
            float4 hv3 = __ldg(hf4 + (size_t)s3 * 32 + lane);
            float v, ex;
            v = l0 + er_h; v = v > 0.f ? v : 0.2f * v; ex = __expf(v);
            denom += ex;
            acc.x += ex * hv0.x; acc.y += ex * hv0.y; acc.z += ex * hv0.z; acc.w += ex * hv0.w;
            v = l1 + er_h; v = v > 0.f ? v : 0.2f * v; ex = __expf(v);
            denom += ex;
            acc.x += ex * hv1.x; acc.y += ex * hv1.y; acc.z += ex * hv1.z; acc.w += ex * hv1.w;
            v = l2 + er_h; v = v > 0.f ? v : 0.2f * v; ex = __expf(v);
            denom += ex;
            acc.x += ex * hv2.x; acc.y += ex * hv2.y; acc.z += ex * hv2.z; acc.w += ex * hv2.w;
            v = l3 + er_h; v = v > 0.f ? v : 0.2f * v; ex = __expf(v);
            denom += ex;
            acc.x += ex * hv3.x; acc.y += ex * hv3.y; acc.z += ex * hv3.z; acc.w += ex * hv3.w;
        }
        for (; k < m; k++) {
            int s = __shfl_sync(0xffffffffu, sid, k);
            float v = __ldg(g_el + s * 8 + h) + er_h;
            v = v > 0.f ? v : 0.2f * v;
            float ex = __expf(v);
            denom += ex;
            float4 hv = __ldg(hf4 + (size_t)s * 32 + lane);
            acc.x += ex * hv.x; acc.y += ex * hv.y; acc.z += ex * hv.z; acc.w += ex * hv.w;
        }
    }

    float inv = (denom > 0.f) ? (1.f / denom) : 0.f;
    float4 b4 = __ldg((const float4*)bias + lane);
    float4 o;
    o.x = b4.x + acc.x * inv;
    o.y = b4.y + acc.y * inv;
    o.z = b4.z + acc.z * inv;
    o.w = b4.w + acc.w * inv;
    ((float4*)out)[(size_t)n * 32 + lane] = o;
}

extern "C" void kernel_launch(void* const* d_in, const int* in_sizes, int n_in,
                              void* d_out, int out_size) {
    const float* nfeat  = (const float*)d_in[0];
    const float* efeat  = (const float*)d_in[1];
    const int*   src    = (const int*)d_in[2];
    const int*   dst    = (const int*)d_in[3];
    const float* W_fc   = (const float*)d_in[4];
    const float* attn_l = (const float*)d_in[5];
    const float* attn_r = (const float*)d_in[6];
    const float* bias   = (const float*)d_in[7];
    const float* W_e    = (const float*)d_in[8];
    const float* b_e    = (const float*)d_in[9];
    float* out = (float*)d_out;

    static cudaStream_t sA = nullptr, sB = nullptr;
    static cudaEvent_t eRoot = nullptr, eG0 = nullptr, ePrep = nullptr, eAtt = nullptr;
    if (!sA) {
        cudaStreamCreateWithFlags(&sA, cudaStreamNonBlocking);
        cudaStreamCreateWithFlags(&sB, cudaStreamNonBlocking);
        cudaEventCreateWithFlags(&eRoot, cudaEventDisableTiming);
        cudaEventCreateWithFlags(&eG0, cudaEventDisableTiming);
        cudaEventCreateWithFlags(&ePrep, cudaEventDisableTiming);
        cudaEventCreateWithFlags(&eAtt, cudaEventDisableTiming);
    }

    const int SMEM = 131072;  // 64KB sA + 64KB sW
    cudaFuncSetAttribute(k_gemm2<0>, cudaFuncAttributeMaxDynamicSharedMemorySize, SMEM);
    cudaFuncSetAttribute(k_gemm2<1>, cudaFuncAttributeMaxDynamicSharedMemorySize, SMEM);

    // fork: GEMM0 on sA runs concurrently with prep chain
    cudaEventRecord(eRoot, 0);
    cudaStreamWaitEvent(sA, eRoot, 0);
    k_gemm2<0><<<(NN + 127) / 128, 256, SMEM, sA>>>(nfeat, W_fc, attn_l, attn_r, b_e, out);
    cudaEventRecord(eG0, sA);

    // prep chain on main stream
    k_zero<<<(NN + 255) / 256, 256>>>();
    k_hist<<<(NE + 255) / 256, 256>>>(dst);
    k_scan<<<1, 1024>>>();
    k_scatter<<<(NE + 255) / 256, 256>>>(src, dst);
    cudaEventRecord(ePrep, 0);

    // esum (needs CSR only) on main stream, concurrent with att on sB
    k_esum<<<(NN * 32 + 255) / 256, 256>>>(efeat);

    cudaStreamWaitEvent(sB, ePrep, 0);
    cudaStreamWaitEvent(sB, eG0, 0);
    k_att<<<(NN * 32 + 255) / 256, 256, 0, sB>>>(bias, out);
    cudaEventRecord(eAtt, sB);

    // join: GEMM1 needs esum (main-stream order) + att + gemm0
    cudaStreamWaitEvent(0, eAtt, 0);
    k_gemm2<1><<<(NN + 127) / 128, 256, SMEM>>>(nfeat, W_e, attn_l, attn_r, b_e, out);
}

// round 11
// speedup vs baseline: 1.7232x; 1.1219x over previous
#include <cuda_runtime.h>
#include <cuda_bf16.h>

#define NN 50000
#define NE 800000
#define SCAN_B 196   // ceil(NN/256)

// ---- device scratch (static: no allocation allowed) ----
__device__ float g_hf[(size_t)NN * 128];     // nfeat @ W_fc
__device__ float g_ssum[(size_t)NN * 128];   // segment_sum(efeat, dst)
__device__ float g_el[NN * 8];
__device__ float g_er[NN * 8];
__device__ int   g_cnt[NN];                  // in-degree
__device__ int   g_off[NN + 1];              // CSR offsets
__device__ int   g_cur[NN];                  // scatter cursors
__device__ int   g_bsum[SCAN_B];             // per-block totals
__device__ int   g_boff[SCAN_B];             // per-block offsets
__device__ int2  g_csr[NE];                  // (src, edge_id) sorted by dst

__device__ __forceinline__ float f2lo(unsigned long long v) {
    return __uint_as_float((unsigned)v);
}
__device__ __forceinline__ float f2hi(unsigned long long v) {
    return __uint_as_float((unsigned)(v >> 32));
}

// ---- zero histogram ----
__global__ void k_zero() {
    int i = blockIdx.x * blockDim.x + threadIdx.x;
    if (i < NN) g_cnt[i] = 0;
}

// ---- histogram of dst ----
__global__ void k_hist(const int* __restrict__ dst) {
    int e = blockIdx.x * blockDim.x + threadIdx.x;
    if (e < NE) atomicAdd(&g_cnt[__ldg(dst + e)], 1);
}

// ---- phase 1: block-local exclusive scan + block totals ----
__global__ void __launch_bounds__(256)
k_scan1() {
    __shared__ int wsum[8];
    int tid = threadIdx.x;
    int i = blockIdx.x * 256 + tid;
    int v = (i < NN) ? g_cnt[i] : 0;
    int x = v;
#pragma unroll
    for (int o = 1; o < 32; o <<= 1) {
        int y = __shfl_up_sync(0xffffffffu, x, o);
        if ((tid & 31) >= o) x += y;
    }
    if ((tid & 31) == 31) wsum[tid >> 5] = x;
    __syncthreads();
    if (tid < 8) {
        int w = wsum[tid];
#pragma unroll
        for (int o = 1; o < 8; o <<= 1) {
            int y = __shfl_up_sync(0xffu, w, o);
            if (tid >= o) w += y;
        }
        wsum[tid] = w;
    }
    __syncthreads();
    int excl = x - v + ((tid >= 32) ? wsum[(tid >> 5) - 1] : 0);
    if (i < NN) g_off[i] = excl;      // block-local exclusive, fixed in phase 3
    if (tid == 255) g_bsum[blockIdx.x] = excl + v;
}

// ---- phase 2: scan the block totals (1 block) ----
__global__ void __launch_bounds__(256)
k_scan2() {
    __shared__ int wsum[8];
    int tid = threadIdx.x;
    int v = (tid < SCAN_B) ? g_bsum[tid] : 0;
    int x = v;
#pragma unroll
    for (int o = 1; o < 32; o <<= 1) {
        int y = __shfl_up_sync(0xffffffffu, x, o);
        if ((tid & 31) >= o) x += y;
    }
    if ((tid & 31) == 31) wsum[tid >> 5] = x;
    __syncthreads();
    if (tid < 8) {
        int w = wsum[tid];
#pragma unroll
        for (int o = 1; o < 8; o <<= 1) {
            int y = __shfl_up_sync(0xffu, w, o);
            if (tid >= o) w += y;
        }
        wsum[tid] = w;
    }
    __syncthreads();
    int incl = x + ((tid >= 32) ? wsum[(tid >> 5) - 1] : 0);
    if (tid < SCAN_B) g_boff[tid] = incl - v;   // exclusive
    if (tid == SCAN_B - 1) g_off[NN] = incl;    // total = NE
}

// ---- phase 3: add block offsets ----
__global__ void __launch_bounds__(256)
k_scan3() {
    int i = blockIdx.x * 256 + threadIdx.x;
    if (i >= NN) return;
    int off = g_off[i] + g_boff[blockIdx.x];
    g_off[i] = off;
    g_cur[i] = off;
}

// ---- scatter edges into CSR buckets ----
__global__ void k_scatter(const int* __restrict__ src, const int* __restrict__ dst) {
    int e = blockIdx.x * blockDim.x + threadIdx.x;
    if (e >= NE) return;
    int d = __ldg(dst + e);
    int pos = atomicAdd(&g_cur[d], 1);
    g_csr[pos] = make_int2(__ldg(src + e), e);
}

// ---- GEMM [128 rows x 128 cols] per block, f32x2 packed FMA ----
template <int MODE>
__global__ void __launch_bounds__(256)
k_gemm2(const float* __restrict__ A, const float* __restrict__ W,
        const float* __restrict__ attn_l, const float* __restrict__ attn_r,
        const float* __restrict__ b_e, float* __restrict__ out) {
    extern __shared__ float smem[];
    float2* sA = (float2*)smem;          // sA[p*128 + k] = (row2p[k], row2p+1[k])
    float*  sW = smem + 16384;           // sW[k*128 + c]
    int t = threadIdx.x;
    int row0 = blockIdx.x * 128;
    int nrows = NN - row0; if (nrows > 128) nrows = 128;
    const float* Ap = (MODE == 1) ? (const float*)g_ssum : A;

    {
        const float4* W4 = (const float4*)W;
        float4* sW4 = (float4*)sW;
#pragma unroll
        for (int i = t; i < 4096; i += 256) sW4[i] = __ldg(W4 + i);
    }
    {
        const float4* A4 = (const float4*)Ap + (size_t)row0 * 32;
        for (int i = t; i < 2048; i += 256) {
            int p = i >> 5, kq = i & 31;
            float4 a0 = (2 * p < nrows) ? __ldg(A4 + (size_t)(2 * p) * 32 + kq)
                                        : make_float4(0.f, 0.f, 0.f, 0.f);
            float4 a1 = (2 * p + 1 < nrows) ? __ldg(A4 + (size_t)(2 * p + 1) * 32 + kq)
                                            : make_float4(0.f, 0.f, 0.f, 0.f);
            float2* d2 = sA + p * 128 + kq * 4;
            d2[0] = make_float2(a0.x, a1.x);
            d2[1] = make_float2(a0.y, a1.y);
            d2[2] = make_float2(a0.z, a1.z);
            d2[3] = make_float2(a0.w, a1.w);
        }
    }
    __syncthreads();

    int lane = t & 31;   // cols 4*lane .. 4*lane+3
    int wrp  = t >> 5;   // rowpairs 8*wrp..+7 (rows 16*wrp..+15)
    int c0 = lane * 4;
    const unsigned long long* sA64 =
        (const unsigned long long*)(sA + wrp * 8 * 128);

    unsigned long long acc[8][4];
#pragma unroll
    for (int j = 0; j < 8; j++)
#pragma unroll
        for (int q = 0; q < 4; q++) acc[j][q] = 0ull;

#pragma unroll 4
    for (int k = 0; k < 128; k++) {
        float4 w4 = *(const float4*)(sW + k * 128 + c0);
        unsigned long long w2[4];
        {
            unsigned wx = __float_as_uint(w4.x), wy = __float_as_uint(w4.y);
            unsigned wz = __float_as_uint(w4.z), ww = __float_as_uint(w4.w);
            asm("mov.b64 %0, {%1,%1};" : "=l"(w2[0]) : "r"(wx));
            asm("mov.b64 %0, {%1,%1};" : "=l"(w2[1]) : "r"(wy));
            asm("mov.b64 %0, {%1,%1};" : "=l"(w2[2]) : "r"(wz));
            asm("mov.b64 %0, {%1,%1};" : "=l"(w2[3]) : "r"(ww));
        }
#pragma unroll
        for (int j = 0; j < 8; j++) {
            unsigned long long a2 = sA64[j * 128 + k];
            asm("fma.rn.f32x2 %0, %1, %2, %0;" : "+l"(acc[j][0]) : "l"(a2), "l"(w2[0]));
            asm("fma.rn.f32x2 %0, %1, %2, %0;" : "+l"(acc[j][1]) : "l"(a2), "l"(w2[1]));
            asm("fma.rn.f32x2 %0, %1, %2, %0;" : "+l"(acc[j][2]) : "l"(a2), "l"(w2[2]));
            asm("fma.rn.f32x2 %0, %1, %2, %0;" : "+l"(acc[j][3]) : "l"(a2), "l"(w2[3]));
        }
    }

    if (MODE == 0) {
        float4 al4 = __ldg((const float4*)attn_l + lane);
        float4 ar4 = __ldg((const float4*)attn_r + lane);
#pragma unroll
        for (int j = 0; j < 8; j++) {
            int re = row0 + wrp * 16 + 2 * j;
#pragma unroll
            for (int half = 0; half < 2; half++) {
                int n = re + half;
                if (n >= NN) continue;
                float4 v;
                if (half == 0)
                    v = make_float4(f2lo(acc[j][0]), f2lo(acc[j][1]),
                                    f2lo(acc[j][2]), f2lo(acc[j][3]));
                else
                    v = make_float4(f2hi(acc[j][0]), f2hi(acc[j][1]),
                                    f2hi(acc[j][2]), f2hi(acc[j][3]));
                ((float4*)g_hf)[(size_t)n * 32 + lane] = v;
                float l = v.x * al4.x + v.y * al4.y + v.z * al4.z + v.w * al4.w;
                float r = v.x * ar4.x + v.y * ar4.y + v.z * ar4.z + v.w * ar4.w;
                l += __shfl_down_sync(0xffffffffu, l, 1, 4);
                l += __shfl_down_sync(0xffffffffu, l, 2, 4);
                r += __shfl_down_sync(0xffffffffu, r, 1, 4);
                r += __shfl_down_sync(0xffffffffu, r, 2, 4);
                if ((lane & 3) == 0) {
                    g_el[n * 8 + (lane >> 2)] = l;
                    g_er[n * 8 + (lane >> 2)] = r;
                }
            }
        }
    } else {
        float4 be4 = __ldg((const float4*)b_e + lane);
#pragma unroll
        for (int j = 0; j < 8; j++) {
            int re = row0 + wrp * 16 + 2 * j;
#pragma unroll
            for (int half = 0; half < 2; half++) {
                int n = re + half;
                if (n >= NN) continue;
                float4 v;
                if (half == 0)
                    v = make_float4(f2lo(acc[j][0]), f2lo(acc[j][1]),
                                    f2lo(acc[j][2]), f2lo(acc[j][3]));
                else
                    v = make_float4(f2hi(acc[j][0]), f2hi(acc[j][1]),
                                    f2hi(acc[j][2]), f2hi(acc[j][3]));
                float deg = (float)__ldg(g_cnt + n);
                float invd = 1.f / fmaxf(deg, 1.f);
                float invp = 1.f / (deg + 1.f);
                float bs = (deg > 0.f) ? 1.f : 0.f;
                float4 o4 = ((float4*)out)[(size_t)n * 32 + lane];
                float4 h4 = ((const float4*)g_hf)[(size_t)n * 32 + lane];
                o4.x += v.x * invd + be4.x * bs + h4.x * invp;
                o4.y += v.y * invd + be4.y * bs + h4.y * invp;
                o4.z += v.z * invd + be4.z * bs + h4.z * invp;
                o4.w += v.w * invd + be4.w * bs + h4.w * invp;
                ((float4*)out)[(size_t)n * 32 + lane] = o4;
            }
        }
    }
}

// ---- efeat segment-sum only (DRAM-bound), warp per node ----
__global__ void __launch_bounds__(256)
k_esum(const float* __restrict__ efeat) {
    int warp = (blockIdx.x * blockDim.x + threadIdx.x) >> 5;
    if (warp >= NN) return;
    int lane = threadIdx.x & 31;
    int beg = __ldg(g_off + warp);
    int end = __ldg(g_off + warp + 1);
    const float4* ef4 = (const float4*)efeat;
    float4 ss = make_float4(0.f, 0.f, 0.f, 0.f);

    for (int base = beg; base < end; base += 32) {
        int m = end - base; if (m > 32) m = 32;
        int eid = (lane < m) ? __ldg(&g_csr[base + lane].y) : 0;
        int k = 0;
        for (; k + 4 <= m; k += 4) {
            int e0 = __shfl_sync(0xffffffffu, eid, k + 0);
            int e1 = __shfl_sync(0xffffffffu, eid, k + 1);
            int e2 = __shfl_sync(0xffffffffu, eid, k + 2);
            int e3 = __shfl_sync(0xffffffffu, eid, k + 3);
            float4 v0 = __ldg(ef4 + (size_t)e0 * 32 + lane);
            float4 v1 = __ldg(ef4 + (size_t)e1 * 32 + lane);
            float4 v2 = __ldg(ef4 + (size_t)e2 * 32 + lane);
            float4 v3 = __ldg(ef4 + (size_t)e3 * 32 + lane);
            ss.x += v0.x + v1.x + v2.x + v3.x;
            ss.y += v0.y + v1.y + v2.y + v3.y;
            ss.z += v0.z + v1.z + v2.z + v3.z;
            ss.w += v0.w + v1.w + v2.w + v3.w;
        }
        for (; k < m; k++) {
            int e = __shfl_sync(0xffffffffu, eid, k);
            float4 v = __ldg(ef4 + (size_t)e * 32 + lane);
            ss.x += v.x; ss.y += v.y; ss.z += v.z; ss.w += v.w;
        }
    }
    ((float4*)g_ssum)[(size_t)warp * 32 + lane] = ss;
}

// ---- attention aggregation only (L2-bound), warp per node ----
__global__ void __launch_bounds__(256)
k_att(const float* __restrict__ bias, float* __restrict__ out) {
    int warp = (blockIdx.x * blockDim.x + threadIdx.x) >> 5;
    if (warp >= NN) return;
    int lane = threadIdx.x & 31;
    int n = warp;
    int beg = __ldg(g_off + n);
    int end = __ldg(g_off + n + 1);
    int h = lane >> 2;
    float er_h = __ldg(g_er + n * 8 + h);

    float4 acc = make_float4(0.f, 0.f, 0.f, 0.f);
    float denom = 0.f;
    const float4* hf4 = (const float4*)g_hf;

    for (int base = beg; base < end; base += 32) {
        int m = end - base; if (m > 32) m = 32;
        int sid = (lane < m) ? __ldg(&g_csr[base + lane].x) : 0;
        int k = 0;
        for (; k + 4 <= m; k += 4) {
            int s0 = __shfl_sync(0xffffffffu, sid, k + 0);
            int s1 = __shfl_sync(0xffffffffu, sid, k + 1);
            int s2 = __shfl_sync(0xffffffffu, sid, k + 2);
            int s3 = __shfl_sync(0xffffffffu, sid, k + 3);
            float l0 = __ldg(g_el + s0 * 8 + h);
            float l1 = __ldg(g_el + s1 * 8 + h);
            float l2 = __ldg(g_el + s2 * 8 + h);
            float l3 = __ldg(g_el + s3 * 8 + h);
            float4 hv0 = __ldg(hf4 + (size_t)s0 * 32 + lane);
            float4 hv1 = __ldg(hf4 + (size_t)s1 * 32 + lane);
            float4 hv2 = __ldg(hf4 + (size_t)s2 * 32 + lane);
            float4 hv3 = __ldg(hf4 + (size_t)s3 * 32 + lane);
            float v, ex;
            v = l0 + er_h; v = v > 0.f ? v : 0.2f * v; ex = __expf(v);
            denom += ex;
            acc.x += ex * hv0.x; acc.y += ex * hv0.y; acc.z += ex * hv0.z; acc.w += ex * hv0.w;
            v = l1 + er_h; v = v > 0.f ? v : 0.2f * v; ex = __expf(v);
            denom += ex;
            acc.x += ex * hv1.x; acc.y += ex * hv1.y; acc.z += ex * hv1.z; acc.w += ex * hv1.w;
            v = l2 + er_h; v = v > 0.f ? v : 0.2f * v; ex = __expf(v);
            denom += ex;
            acc.x += ex * hv2.x; acc.y += ex * hv2.y; acc.z += ex * hv2.z; acc.w += ex * hv2.w;
            v = l3 + er_h; v = v > 0.f ? v : 0.2f * v; ex = __expf(v);
            denom += ex;
            acc.x += ex * hv3.x; acc.y += ex * hv3.y; acc.z += ex * hv3.z; acc.w += ex * hv3.w;
        }
        for (; k < m; k++) {
            int s = __shfl_sync(0xffffffffu, sid, k);
            float v = __ldg(g_el + s * 8 + h) + er_h;
            v = v > 0.f ? v : 0.2f * v;
            float ex = __expf(v);
            denom += ex;
            float4 hv = __ldg(hf4 + (size_t)s * 32 + lane);
            acc.x += ex * hv.x; acc.y += ex * hv.y; acc.z += ex * hv.z; acc.w += ex * hv.w;
        }
    }

    float inv = (denom > 0.f) ? (1.f / denom) : 0.f;
    float4 b4 = __ldg((const float4*)bias + lane);
    float4 o;
    o.x = b4.x + acc.x * inv;
    o.y = b4.y + acc.y * inv;
    o.z = b4.z + acc.z * inv;
    o.w = b4.w + acc.w * inv;
    ((float4*)out)[(size_t)n * 32 + lane] = o;
}

extern "C" void kernel_launch(void* const* d_in, const int* in_sizes, int n_in,
                              void* d_out, int out_size) {
    const float* nfeat  = (const float*)d_in[0];
    const float* efeat  = (const float*)d_in[1];
    const int*   src    = (const int*)d_in[2];
    const int*   dst    = (const int*)d_in[3];
    const float* W_fc   = (const float*)d_in[4];
    const float* attn_l = (const float*)d_in[5];
    const float* attn_r = (const float*)d_in[6];
    const float* bias   = (const float*)d_in[7];
    const float* W_e    = (const float*)d_in[8];
    const float* b_e    = (const float*)d_in[9];
    float* out = (float*)d_out;

    static cudaStream_t sA = nullptr, sB = nullptr;
    static cudaEvent_t eRoot = nullptr, eG0 = nullptr, ePrep = nullptr, eAtt = nullptr;
    if (!sA) {
        cudaStreamCreateWithFlags(&sA, cudaStreamNonBlocking);
        cudaStreamCreateWithFlags(&sB, cudaStreamNonBlocking);
        cudaEventCreateWithFlags(&eRoot, cudaEventDisableTiming);
        cudaEventCreateWithFlags(&eG0, cudaEventDisableTiming);
        cudaEventCreateWithFlags(&ePrep, cudaEventDisableTiming);
        cudaEventCreateWithFlags(&eAtt, cudaEventDisableTiming);
    }

    const int SMEM = 131072;  // 64KB sA + 64KB sW
    cudaFuncSetAttribute(k_gemm2<0>, cudaFuncAttributeMaxDynamicSharedMemorySize, SMEM);
    cudaFuncSetAttribute(k_gemm2<1>, cudaFuncAttributeMaxDynamicSharedMemorySize, SMEM);

    // fork: GEMM0 on sA runs concurrently with prep chain
    cudaEventRecord(eRoot, 0);
    cudaStreamWaitEvent(sA, eRoot, 0);
    k_gemm2<0><<<(NN + 127) / 128, 256, SMEM, sA>>>(nfeat, W_fc, attn_l, attn_r, b_e, out);
    cudaEventRecord(eG0, sA);

    // prep chain on main stream (multi-block scan)
    k_zero<<<(NN + 255) / 256, 256>>>();
    k_hist<<<(NE + 255) / 256, 256>>>(dst);
    k_scan1<<<SCAN_B, 256>>>();
    k_scan2<<<1, 256>>>();
    k_scan3<<<SCAN_B, 256>>>();
    k_scatter<<<(NE + 255) / 256, 256>>>(src, dst);
    cudaEventRecord(ePrep, 0);

    // esum (needs CSR only) on main stream, concurrent with att on sB
    k_esum<<<(NN * 32 + 255) / 256, 256>>>(efeat);

    cudaStreamWaitEvent(sB, ePrep, 0);
    cudaStreamWaitEvent(sB, eG0, 0);
    k_att<<<(NN * 32 + 255) / 256, 256, 0, sB>>>(bias, out);
    cudaEventRecord(eAtt, sB);

    // join: GEMM1 needs esum (main-stream order) + att + gemm0
    cudaStreamWaitEvent(0, eAtt, 0);
    k_gemm2<1><<<(NN + 127) / 128, 256, SMEM>>>(nfeat, W_e, attn_l, attn_r, b_e, out);
}